// round 6
// baseline (speedup 1.0000x reference)
#include <cuda_runtime.h>
#include <cuda_bf16.h>

// Fixed problem shape (from reference setup_inputs): B=32, H=W=768.
// LEVELS=(1,2,3) -> finest grid 8x8 regions of 96x96.
#define IMG_H   768
#define IMG_W   768
#define IMG_N   (IMG_H * IMG_W)          // 589824
#define REG     96                       // region side at level 3
#define NREG    64                       // 8x8 regions per image
#define MAXB    32                       // batch for this problem

__device__ float g_sqsum[MAXB * NREG];        // per-region sum of (p-g)^2
__device__ float g_rdiff[MAXB * NREG];        // per-region sum of (p-g)
__device__ unsigned int g_counter = 0;        // last-block-done counter

// ---------------------------------------------------------------------------
// Fused kernel: one block per (batch, region); region = 96x96 floats.
// Inner loop front-batches 6 LDG.128 per step (3 pred + 3 gt float4s) to
// raise per-warp MLP; occupancy relaxed to 6 blocks/SM to give ptxas the
// registers to keep the batch live. __ldcs = evict-first (read-once data).
// The LAST arriving block performs the final reduction via a smem-staged,
// fully-parallel pyramid.
// ---------------------------------------------------------------------------
__global__ __launch_bounds__(256, 6)
void saf_fused_kernel(const float* __restrict__ pred,
                      const float* __restrict__ gt,
                      const float* __restrict__ rgb,
                      const float* __restrict__ thermal,
                      float* __restrict__ out,
                      int B)
{
    const int blk = blockIdx.x;
    const int b   = blk >> 6;        // batch
    const int r   = blk & 63;        // region index 0..63
    const int ry  = r >> 3;
    const int rx  = r & 7;

    const size_t base = (size_t)b * IMG_N + (size_t)ry * REG * IMG_W + (size_t)rx * REG;
    const float4* __restrict__ p4 = reinterpret_cast<const float4*>(pred + base);
    const float4* __restrict__ g4 = reinterpret_cast<const float4*>(gt   + base);
    // region: 96 rows x 24 float4 per row; row stride = 768 floats = 192 float4

    const int t = threadIdx.x;
    float dsum = 0.0f;
    float ssum = 0.0f;

#pragma unroll
    for (int bch = 0; bch < 3; ++bch) {
        // precompute the 3 offsets for this batch
        int off0, off1, off2;
        {
            int idx = t + (3 * bch + 0) * 256;
            int row = idx / 24;  off0 = row * 192 + (idx - row * 24);
            idx = t + (3 * bch + 1) * 256;
            row = idx / 24;      off1 = row * 192 + (idx - row * 24);
            idx = t + (3 * bch + 2) * 256;
            row = idx / 24;      off2 = row * 192 + (idx - row * 24);
        }
        // front-batched loads: 6 independent LDG.128 in flight
        float4 pa0 = __ldcs(&p4[off0]);
        float4 pa1 = __ldcs(&p4[off1]);
        float4 pa2 = __ldcs(&p4[off2]);
        float4 ga0 = __ldcs(&g4[off0]);
        float4 ga1 = __ldcs(&g4[off1]);
        float4 ga2 = __ldcs(&g4[off2]);

        float d;
        d = pa0.x - ga0.x; dsum += d; ssum += d * d;
        d = pa0.y - ga0.y; dsum += d; ssum += d * d;
        d = pa0.z - ga0.z; dsum += d; ssum += d * d;
        d = pa0.w - ga0.w; dsum += d; ssum += d * d;
        d = pa1.x - ga1.x; dsum += d; ssum += d * d;
        d = pa1.y - ga1.y; dsum += d; ssum += d * d;
        d = pa1.z - ga1.z; dsum += d; ssum += d * d;
        d = pa1.w - ga1.w; dsum += d; ssum += d * d;
        d = pa2.x - ga2.x; dsum += d; ssum += d * d;
        d = pa2.y - ga2.y; dsum += d; ssum += d * d;
        d = pa2.z - ga2.z; dsum += d; ssum += d * d;
        d = pa2.w - ga2.w; dsum += d; ssum += d * d;
    }

    // warp reduce
#pragma unroll
    for (int o = 16; o > 0; o >>= 1) {
        dsum += __shfl_xor_sync(0xFFFFFFFFu, dsum, o);
        ssum += __shfl_xor_sync(0xFFFFFFFFu, ssum, o);
    }

    __shared__ float s_d[8];
    __shared__ float s_s[8];
    const int wid = t >> 5;
    const int lid = t & 31;
    if (lid == 0) { s_d[wid] = dsum; s_s[wid] = ssum; }
    __syncthreads();

    if (t == 0) {
        float dd = 0.0f, ss = 0.0f;
#pragma unroll
        for (int w = 0; w < 8; ++w) { dd += s_d[w]; ss += s_s[w]; }
        g_rdiff[blk] = dd;
        g_sqsum[blk] = ss;
    }

    // ----- last-block-done handshake -----
    __shared__ unsigned int s_last;
    __threadfence();                      // make partials visible before counting
    if (t == 0) {
        unsigned int old = atomicAdd(&g_counter, 1u);
        s_last = (old == (unsigned int)(gridDim.x - 1));
    }
    __syncthreads();
    if (!s_last) return;
    __threadfence();                      // reader-side ordering
    if (t == 0) g_counter = 0;            // reset for next graph replay

    // ===== finish phase: smem-staged parallel pyramid =====
    const int nblk = B * NREG;            // 2048

    __shared__ float sm_r[MAXB * 64];     // 8 KB
    __shared__ float sm_d4[MAXB * 16];    // 2 KB
    __shared__ float sm_d2[MAXB * 4];     // 0.5 KB

    float sq = 0.0f;
    for (int i = t; i < nblk; i += 256) {
        sq += __ldcg(&g_sqsum[i]);
        sm_r[i] = __ldcg(&g_rdiff[i]);
    }
    __syncthreads();

    // level 3: sum |r| over all 2048
    float l3 = 0.0f;
    for (int i = t; i < nblk; i += 256) l3 += fabsf(sm_r[i]);

    // level 2: B*16 = 512 cells
    float l2 = 0.0f;
    for (int j = t; j < B * 16; j += 256) {
        const int bb2 = j >> 4;
        const int q   = j & 15;
        const int qi  = q >> 2;
        const int qj  = q & 3;
        const float* rr = &sm_r[bb2 * 64];
        float s = rr[(2 * qi) * 8 + 2 * qj] + rr[(2 * qi) * 8 + 2 * qj + 1]
                + rr[(2 * qi + 1) * 8 + 2 * qj] + rr[(2 * qi + 1) * 8 + 2 * qj + 1];
        sm_d4[j] = s;
        l2 += fabsf(s);
    }
    __syncthreads();

    // level 1: B*4 = 128 cells
    float l1 = 0.0f;
    for (int j = t; j < B * 4; j += 256) {
        const int bb2 = j >> 2;
        const int q   = j & 3;
        const int qi  = q >> 1;
        const int qj  = q & 1;
        const float* dd = &sm_d4[bb2 * 16];
        float s = dd[(2 * qi) * 4 + 2 * qj] + dd[(2 * qi) * 4 + 2 * qj + 1]
                + dd[(2 * qi + 1) * 4 + 2 * qj] + dd[(2 * qi + 1) * 4 + 2 * qj + 1];
        sm_d2[j] = s;
        l1 += fabsf(s);
    }
    __syncthreads();

    // count loss: |total per batch| (sum of the 4 level-1 cells)
    float cnt = 0.0f;
    for (int j = t; j < B; j += 256) {
        float s = sm_d2[j * 4] + sm_d2[j * 4 + 1] + sm_d2[j * 4 + 2] + sm_d2[j * 4 + 3];
        cnt += fabsf(s);
    }

    // domain CE: rgb label 0, thermal label 1
    float dom = 0.0f;
    for (int j = t; j < B; j += 256) {
        float x0 = rgb[2 * j], x1 = rgb[2 * j + 1];
        float m  = fmaxf(x0, x1);
        float lse = m + logf(expf(x0 - m) + expf(x1 - m));
        dom += lse - x0;
        float y0 = thermal[2 * j], y1 = thermal[2 * j + 1];
        m   = fmaxf(y0, y1);
        lse = m + logf(expf(y0 - m) + expf(y1 - m));
        dom += lse - y1;
    }

    float reg = l1 + l2 + l3;

    __shared__ float s_sq[256], s_cnt[256], s_reg[256], s_dom[256];
    s_sq[t] = sq; s_cnt[t] = cnt; s_reg[t] = reg; s_dom[t] = dom;
    __syncthreads();
#pragma unroll
    for (int o = 128; o > 0; o >>= 1) {
        if (t < o) {
            s_sq[t]  += s_sq[t + o];
            s_cnt[t] += s_cnt[t + o];
            s_reg[t] += s_reg[t + o];
            s_dom[t] += s_dom[t + o];
        }
        __syncthreads();
    }

    if (t == 0) {
        float invB = 1.0f / (float)B;
        float density  = s_sq[0] / ((float)B * (float)IMG_N);
        float count_l  = s_cnt[0] * invB;
        float regional = s_reg[0] * invB / (3.0f * 64.0f);  // len(LEVELS)*last_cells^2
        float domain   = (s_dom[0] * invB) * 0.5f;          // (ce_rgb + ce_th)/2
        // W_DENSITY=100, W_COUNT=0.001, W_REGIONAL=1.0, W_DOMAIN=0.5
        out[0] = 100.0f * density + 0.001f * count_l + 1.0f * regional + 0.5f * domain;
    }
}

extern "C" void kernel_launch(void* const* d_in, const int* in_sizes, int n_in,
                              void* d_out, int out_size)
{
    const float* pred    = (const float*)d_in[0];
    const float* gt      = (const float*)d_in[1];
    const float* rgb     = (const float*)d_in[2];
    const float* thermal = (const float*)d_in[3];
    float* out = (float*)d_out;

    const int B = in_sizes[0] / IMG_N;   // 32 for this problem

    saf_fused_kernel<<<B * NREG, 256>>>(pred, gt, rgb, thermal, out, B);
}